// round 5
// baseline (speedup 1.0000x reference)
#include <cuda_runtime.h>
#include <cuda_bf16.h>

// BatchRNNCustom: pack padded (B,S,D) sequences by descending length.
// Output layout (fp32, concatenated in reference return order):
//   [0, B*S*D)            packed_data
//   [B*S*D, +S)           batch_sizes
//   [.. +B)               sorted_indices
//   [.. +B)               unsorted_indices
//
// Pipeline:
//   1) meta_kernel : dtype-detect lengths, stable rank-sort (B=64), suffix
//                    sums, then offsets[t] = t*m(t) + suffix[m(t)] via 6-step
//                    binary search per t. 1 block, 1024 threads.
//   2) map_kernel  : valid row r -> {t, src_batch} LUT (1 MB).
//   3) pack_kernel : 8 rows per 128-thread block, MLP=8 float4 streaming
//                    gather/scatter. Rows >= total are zeroed.

#define BB 64
#define SS 2048
#define DD 512

__device__ int  g_sortidx[BB];      // rank -> original batch index
__device__ int  g_offsets[SS + 1];  // offsets[t] = sum_b min(len_b, t)
__device__ int2 g_map[BB * SS];     // valid row r -> {t, src_batch}

// ---------------------------------------------------------------------------
// Kernel 1: metadata. Single block, 1024 threads.
// ---------------------------------------------------------------------------
__global__ void meta_kernel(const int* __restrict__ lengths_raw,
                            float* __restrict__ out, long long out_size) {
    __shared__ int sraw[BB];         // lengths by original index
    __shared__ int slen[BB];         // lengths sorted descending
    __shared__ int ssuf[BB + 1];     // ssuf[k] = sum_{j>=k} slen[j]
    __shared__ int s_is64;
    const int tid = threadIdx.x;

    // dtype detection: lengths >= 1, so int64 (LE) has all odd words == 0.
    if (tid == 0) s_is64 = 1;
    __syncthreads();
    if (tid < BB) {
        int w = lengths_raw[tid];
        if ((tid & 1) && w != 0) atomicAnd(&s_is64, 0);
    }
    __syncthreads();
    if (tid < BB) {
        sraw[tid] = s_is64 ? (int)((const long long*)lengths_raw)[tid]
                           : lengths_raw[tid];
    }
    __syncthreads();

    // stable descending rank sort (O(B^2), 64 threads)
    if (tid < BB) {
        int li = sraw[tid];
        int r = 0;
#pragma unroll 8
        for (int j = 0; j < BB; j++) {
            int lj = sraw[j];
            if (lj > li || (lj == li && j < tid)) r++;
        }
        slen[r] = li;
        g_sortidx[r] = tid;

        long long tail = (long long)BB * SS * DD + SS;
        if (out_size >= tail + 2 * BB) {
            out[tail + r] = (float)tid;       // sorted_indices[r]   = tid
            out[tail + BB + tid] = (float)r;  // unsorted_indices[tid] = r
        }
    }
    __syncthreads();

    // suffix sums of sorted lengths (64 threads, O(B) each — trivial)
    if (tid <= BB) {
        int s = 0;
        for (int j = tid; j < BB; j++) s += slen[j];
        ssuf[tid] = s;
    }
    __syncthreads();

    // offsets[t] / batch_sizes[t] via binary search on descending slen:
    //   m(t) = #{slen >= t} = first index with slen[idx] < t
    //   offsets[t]     = t*m(t) + ssuf[m(t)]
    //   batch_sizes[t] = #{slen > t} = m(t+1)
    const long long base = (long long)BB * SS * DD;
    for (int t = tid; t <= SS; t += blockDim.x) {
        // m(t)
        int lo = 0, hi = BB;                 // slen[lo-1] >= t > slen[hi]... find first < t
        while (lo < hi) {
            int mid = (lo + hi) >> 1;
            if (slen[mid] >= t) lo = mid + 1; else hi = mid;
        }
        int m = lo;
        g_offsets[t] = t * m + ssuf[m];

        if (t < SS && out_size >= base + SS) {
            // m(t+1) = #{slen >= t+1} = #{slen > t}
            int t1 = t + 1;
            lo = 0; hi = BB;
            while (lo < hi) {
                int mid = (lo + hi) >> 1;
                if (slen[mid] >= t1) lo = mid + 1; else hi = mid;
            }
            out[base + t] = (float)lo;
        }
    }
}

// ---------------------------------------------------------------------------
// Kernel 2: fill row -> (t, src_batch) LUT. One thread per (t, b) pair.
// ---------------------------------------------------------------------------
__global__ void map_kernel() {
    int idx = blockIdx.x * blockDim.x + threadIdx.x;   // 0 .. B*S-1
    int t = idx >> 6;          // / BB
    int b = idx & (BB - 1);    // % BB
    int off = g_offsets[t];
    int cnt = g_offsets[t + 1] - off;
    if (b < cnt) g_map[off + b] = make_int2(t, g_sortidx[b]);
}

// ---------------------------------------------------------------------------
// Kernel 3: pack. 128-thread block handles 8 consecutive output rows
// (8 x 2 KB). MLP=8 independent float4 streaming loads, then 8 streaming
// stores into a 16 KB contiguous destination region.
// ---------------------------------------------------------------------------
__global__ void __launch_bounds__(128) pack_kernel(const float* __restrict__ in,
                                                   float* __restrict__ out) {
    const int tid = threadIdx.x;
    const int r0 = blockIdx.x * 8;
    const int total = g_offsets[SS];
    const float4* inp = reinterpret_cast<const float4*>(in);

    float4 v[8];
#pragma unroll
    for (int i = 0; i < 8; i++) {
        const int r = r0 + i;
        if (r < total) {
            int2 m = g_map[r];   // uniform per block-slot: {t, src_batch}
            long long srow = (long long)m.y * SS + m.x;
            v[i] = __ldcs(inp + srow * (DD / 4) + tid);
        } else {
            v[i] = make_float4(0.f, 0.f, 0.f, 0.f);
        }
    }

    float4* op = reinterpret_cast<float4*>(out) + (long long)r0 * (DD / 4) + tid;
#pragma unroll
    for (int i = 0; i < 8; i++) __stcs(op + i * (DD / 4), v[i]);
}

extern "C" void kernel_launch(void* const* d_in, const int* in_sizes, int n_in,
                              void* d_out, int out_size) {
    const float* inputs = (const float*)d_in[0];    // (B, S, D) fp32
    // d_in[1]: input_paddings (unused — all zeros)
    const int* lengths_raw = (const int*)d_in[2];   // (B,) int32 or int64
    float* out = (float*)d_out;
    long long osz = (long long)out_size;

    meta_kernel<<<1, 1024>>>(lengths_raw, out, osz);
    map_kernel<<<(BB * SS) / 256, 256>>>();
    pack_kernel<<<(BB * SS) / 8, 128>>>(inputs, out);
}